// round 3
// baseline (speedup 1.0000x reference)
#include <cuda_runtime.h>
#include <cstdint>
#include <cstring>
#include <math.h>

#define N_SAMP 64
#define CCH    3
#define HH     512
#define WW     512
#define OFFS   106   // (ceil(sqrt(2)*512) - 512)//2 = (725-512)//2

struct GridParams {
    int d[N_SAMP];
    int l[N_SAMP];
    int sh[N_SAMP];
    int sw[N_SAMP];
};

// ---------------------------------------------------------------------------
// Host-side Threefry2x32, JAX partitionable path (default since JAX 0.4.36):
//   split(key, n):      key_i  = threefry(key, (0, i))        (fold-like)
//   random_bits 32-bit: bits_i = o0 ^ o1 of threefry(key, (0, i))
//   randint(key,96,224): k1,k2 = split(key,2); span=128 (pow2, <=2^16) so
//       multiplier = (2^16 % 128)^2 % 128 = 0  ->  val = 96 + (bits(k2) & 127)
//   uniform(key): bits from key directly; u = bitcast((b>>9)|0x3f800000)-1
// All params derive from jax.random.key(42) + fixed shapes -> host-computed,
// passed by value (graph-capture legal, no allocations).
// ---------------------------------------------------------------------------
static inline uint32_t rotl32(uint32_t x, int r) { return (x << r) | (x >> (32 - r)); }

static void threefry2x32(uint32_t k0, uint32_t k1, uint32_t x0, uint32_t x1,
                         uint32_t& o0, uint32_t& o1) {
    const uint32_t ks2 = k0 ^ k1 ^ 0x1BD11BDAu;
    x0 += k0; x1 += k1;
    #define TF_R4(a,b,c,dd) \
        x0 += x1; x1 = rotl32(x1,(a)); x1 ^= x0; \
        x0 += x1; x1 = rotl32(x1,(b)); x1 ^= x0; \
        x0 += x1; x1 = rotl32(x1,(c)); x1 ^= x0; \
        x0 += x1; x1 = rotl32(x1,(dd)); x1 ^= x0;
    TF_R4(13,15,26,6);   x0 += k1;  x1 += ks2 + 1u;
    TF_R4(17,29,16,24);  x0 += ks2; x1 += k0  + 2u;
    TF_R4(13,15,26,6);   x0 += k0;  x1 += k1  + 3u;
    TF_R4(17,29,16,24);  x0 += k1;  x1 += ks2 + 4u;
    TF_R4(13,15,26,6);   x0 += ks2; x1 += k0  + 5u;
    #undef TF_R4
    o0 = x0; o1 = x1;
}

// Fold-like split: child i of key = full threefry output block at count (0, i).
static inline void jax_split_child(const uint32_t key[2], uint32_t i, uint32_t out[2]) {
    threefry2x32(key[0], key[1], 0u, i, out[0], out[1]);
}

// Partitionable 32-bit random bits: bits[i] = o0 ^ o1 at count (0, i).
static inline uint32_t jax_bits32(const uint32_t key[2], uint32_t i) {
    uint32_t a, b;
    threefry2x32(key[0], key[1], 0u, i, a, b);
    return a ^ b;
}

static void compute_params(GridParams& p) {
    // jax.random.key(42) -> key data (0, 42)
    const uint32_t root[2] = { 0u, 42u };

    // k1, k2, k3 = split(root, 3)
    uint32_t kd[2], kh[2], kw[2];
    jax_split_child(root, 0u, kd);
    jax_split_child(root, 1u, kh);
    jax_split_child(root, 2u, kw);

    // randint(kd, (64,), 96, 224): internal split; only LOWER bits matter
    // (span=128 pow2 -> multiplier==0). lower bits come from child 1.
    uint32_t kd_lo[2];
    jax_split_child(kd, 1u, kd_lo);

    for (int i = 0; i < N_SAMP; i++) {
        int d = 96 + (int)(jax_bits32(kd_lo, (uint32_t)i) & 127u);
        p.d[i] = d;
        p.l[i] = (d + 1) >> 1;   // ceil(d * 0.5)

        // uniform draws directly from kh / kw (no internal split)
        uint32_t bh = jax_bits32(kh, (uint32_t)i);
        float uh; { uint32_t fb = (bh >> 9) | 0x3F800000u; memcpy(&uh, &fb, 4); uh -= 1.0f; }
        p.sh[i] = (int)floorf(uh * (float)d);

        uint32_t bw = jax_bits32(kw, (uint32_t)i);
        float uw; { uint32_t fb = (bw >> 9) | 0x3F800000u; memcpy(&uw, &fb, 4); uw -= 1.0f; }
        p.sw[i] = (int)floorf(uw * (float)d);
    }
}

// ---------------------------------------------------------------------------
// Streaming elementwise multiply: one float4 per thread, one row per block.
// grid = (512 rows, 3 channels, 64 samples), block = 128 threads.
// ---------------------------------------------------------------------------
__global__ void GridMask_kernel(const float* __restrict__ x,
                                float* __restrict__ y,
                                GridParams p) {
    const int n = blockIdx.z;
    const int c = blockIdx.y;
    const int h = blockIdx.x;
    const int w = threadIdx.x << 2;

    const int d = p.d[n];
    const int l = p.l[n];

    // row keep: ((OFFS + h - st_h) mod d) >= l   (python-style nonneg mod)
    int vr = OFFS + h - p.sh[n];
    int mr = vr % d; if (mr < 0) mr += d;
    const bool row_keep = (mr >= l);

    const size_t base = (((size_t)n * CCH + c) * HH + h) * (size_t)WW + w;
    const float4 v = *reinterpret_cast<const float4*>(x + base);
    float4 o;

    if (!row_keep) {
        o = make_float4(0.f, 0.f, 0.f, 0.f);
    } else {
        int vc = OFFS + w - p.sw[n];
        int mc = vc % d; if (mc < 0) mc += d;
        o.x = (mc >= l) ? v.x : 0.f; if (++mc == d) mc = 0;
        o.y = (mc >= l) ? v.y : 0.f; if (++mc == d) mc = 0;
        o.z = (mc >= l) ? v.z : 0.f; if (++mc == d) mc = 0;
        o.w = (mc >= l) ? v.w : 0.f;
    }
    *reinterpret_cast<float4*>(y + base) = o;
}

extern "C" void kernel_launch(void* const* d_in, const int* in_sizes, int n_in,
                              void* d_out, int out_size) {
    (void)in_sizes; (void)n_in; (void)out_size;
    const float* x = (const float*)d_in[0];
    float* y = (float*)d_out;

    GridParams p;
    compute_params(p);   // deterministic, host-only, ~200 threefry evals

    dim3 grid(HH, CCH, N_SAMP);
    GridMask_kernel<<<grid, WW / 4>>>(x, y, p);
}

// round 5
// speedup vs baseline: 1.1629x; 1.1629x over previous
#include <cuda_runtime.h>
#include <cstdint>
#include <cstring>
#include <math.h>

#define N_SAMP 64
#define CCH    3
#define HH     512
#define WW     512
#define OFFS   106   // (ceil(sqrt(2)*512) - 512)//2 = (725-512)//2

struct MaskBits {
    uint32_t row[N_SAMP][HH / 32];  // 4 KB: row-keep bit per (n, h)
    uint32_t col[N_SAMP][WW / 32];  // 4 KB: col-keep bit per (n, w)
};

// ---------------------------------------------------------------------------
// Host-side Threefry2x32, JAX partitionable path (verified exact in R3):
//   split(key, n):      key_i  = threefry(key, (0, i))
//   random_bits 32-bit: bits_i = o0 ^ o1 of threefry(key, (0, i))
//   randint(key,96,224): k1,k2 = split(key); span=128 pow2 -> 96+(bits(k2)&127)
//   uniform(key): u = bitcast((bits>>9)|0x3f800000) - 1
// ---------------------------------------------------------------------------
static inline uint32_t rotl32(uint32_t x, int r) { return (x << r) | (x >> (32 - r)); }

static void threefry2x32(uint32_t k0, uint32_t k1, uint32_t x0, uint32_t x1,
                         uint32_t& o0, uint32_t& o1) {
    const uint32_t ks2 = k0 ^ k1 ^ 0x1BD11BDAu;
    x0 += k0; x1 += k1;
    #define TF_R4(a,b,c,dd) \
        x0 += x1; x1 = rotl32(x1,(a)); x1 ^= x0; \
        x0 += x1; x1 = rotl32(x1,(b)); x1 ^= x0; \
        x0 += x1; x1 = rotl32(x1,(c)); x1 ^= x0; \
        x0 += x1; x1 = rotl32(x1,(dd)); x1 ^= x0;
    TF_R4(13,15,26,6);   x0 += k1;  x1 += ks2 + 1u;
    TF_R4(17,29,16,24);  x0 += ks2; x1 += k0  + 2u;
    TF_R4(13,15,26,6);   x0 += k0;  x1 += k1  + 3u;
    TF_R4(17,29,16,24);  x0 += k1;  x1 += ks2 + 4u;
    TF_R4(13,15,26,6);   x0 += ks2; x1 += k0  + 5u;
    #undef TF_R4
    o0 = x0; o1 = x1;
}

static inline void jax_split_child(const uint32_t key[2], uint32_t i, uint32_t out[2]) {
    threefry2x32(key[0], key[1], 0u, i, out[0], out[1]);
}

static inline uint32_t jax_bits32(const uint32_t key[2], uint32_t i) {
    uint32_t a, b;
    threefry2x32(key[0], key[1], 0u, i, a, b);
    return a ^ b;
}

static void compute_bits(MaskBits& mb) {
    const uint32_t root[2] = { 0u, 42u };  // jax.random.key(42)

    uint32_t kd[2], kh[2], kw[2];
    jax_split_child(root, 0u, kd);
    jax_split_child(root, 1u, kh);
    jax_split_child(root, 2u, kw);

    uint32_t kd_lo[2];
    jax_split_child(kd, 1u, kd_lo);  // randint uses lower-bits child

    memset(&mb, 0, sizeof(mb));
    for (int i = 0; i < N_SAMP; i++) {
        int d = 96 + (int)(jax_bits32(kd_lo, (uint32_t)i) & 127u);
        int l = (d + 1) >> 1;  // ceil(d * 0.5)

        uint32_t bh = jax_bits32(kh, (uint32_t)i);
        float uh; { uint32_t fb = (bh >> 9) | 0x3F800000u; memcpy(&uh, &fb, 4); uh -= 1.0f; }
        int sh = (int)floorf(uh * (float)d);

        uint32_t bw = jax_bits32(kw, (uint32_t)i);
        float uw; { uint32_t fb = (bw >> 9) | 0x3F800000u; memcpy(&uw, &fb, 4); uw -= 1.0f; }
        int sw = (int)floorf(uw * (float)d);

        for (int h = 0; h < HH; h++) {
            int m = (OFFS + h - sh) % d; if (m < 0) m += d;
            if (m >= l) mb.row[i][h >> 5] |= (1u << (h & 31));
        }
        for (int w = 0; w < WW; w++) {
            int m = (OFFS + w - sw) % d; if (m < 0) m += d;
            if (m >= l) mb.col[i][w >> 5] |= (1u << (w & 31));
        }
    }
}

// ---------------------------------------------------------------------------
// Streaming multiply with load elision. One thread = one (h, w4) position
// across ALL 3 channels (mask is channel-independent): 3 independent
// 16B loads/stores (MLP=3), mask = 2 constant-bank bit extracts.
// Masked-out positions store zeros WITHOUT reading x (~75% read elision).
// grid = (512 rows, 64 samples), block = 128 threads.
// ---------------------------------------------------------------------------
__global__ void GridMask_kernel(const float* __restrict__ x,
                                float* __restrict__ y,
                                const __grid_constant__ MaskBits mb) {
    const int h = blockIdx.x;
    const int n = blockIdx.y;
    const int w = threadIdx.x << 2;

    const bool row_keep = (mb.row[n][h >> 5] >> (h & 31)) & 1u;
    const uint32_t nib  = (mb.col[n][w >> 5] >> (w & 31)) & 0xFu;

    const size_t b0 = (((size_t)n * CCH + 0) * HH + h) * (size_t)WW + w;
    const size_t b1 = b0 + (size_t)HH * WW;
    const size_t b2 = b1 + (size_t)HH * WW;

    if (!row_keep || nib == 0u) {
        const float4 z = make_float4(0.f, 0.f, 0.f, 0.f);
        *reinterpret_cast<float4*>(y + b0) = z;
        *reinterpret_cast<float4*>(y + b1) = z;
        *reinterpret_cast<float4*>(y + b2) = z;
        return;
    }

    // Independent streaming loads (evict-first: keep L2 for dirty output)
    float4 v0 = __ldcs(reinterpret_cast<const float4*>(x + b0));
    float4 v1 = __ldcs(reinterpret_cast<const float4*>(x + b1));
    float4 v2 = __ldcs(reinterpret_cast<const float4*>(x + b2));

    const float mx = (nib & 1u) ? 1.f : 0.f;
    const float my = (nib & 2u) ? 1.f : 0.f;
    const float mz = (nib & 4u) ? 1.f : 0.f;
    const float mw = (nib & 8u) ? 1.f : 0.f;

    v0.x *= mx; v0.y *= my; v0.z *= mz; v0.w *= mw;
    v1.x *= mx; v1.y *= my; v1.z *= mz; v1.w *= mw;
    v2.x *= mx; v2.y *= my; v2.z *= mz; v2.w *= mw;

    *reinterpret_cast<float4*>(y + b0) = v0;
    *reinterpret_cast<float4*>(y + b1) = v1;
    *reinterpret_cast<float4*>(y + b2) = v2;
}

extern "C" void kernel_launch(void* const* d_in, const int* in_sizes, int n_in,
                              void* d_out, int out_size) {
    (void)in_sizes; (void)n_in; (void)out_size;
    const float* x = (const float*)d_in[0];
    float* y = (float*)d_out;

    MaskBits mb;
    compute_bits(mb);  // deterministic, host-only, ~10us; runs once at capture

    dim3 grid(HH, N_SAMP);
    GridMask_kernel<<<grid, WW / 4>>>(x, y, mb);
}